// round 15
// baseline (speedup 1.0000x reference)
#include <cuda_runtime.h>
#include <math.h>

#define NB     64
#define TT     1024
#define ML     256
#define PP     (TT - 1)
#define NTHR   128          // 4 warps: 2 lag-groups x 2 position-halves
#define CPB    16           // CTAs per batch
#define NBLK   (NB * CPB)   // 1024 CTAs
#define GL     8            // lags per group

// Packed f32x2 ops (Blackwell FFMA2/FADD2/FMUL2 — PTX-only, ptxas won't fuse)
#define FMA_F32X2(out, a, b, c) \
    asm("fma.rn.f32x2 %0, %1, %2, %3;" : "=l"(out) : "l"(a), "l"(b), "l"(c))
#define ADD_F32X2(out, a, b) \
    asm("add.rn.f32x2 %0, %1, %2;" : "=l"(out) : "l"(a), "l"(b))
#define MUL_F32X2(out, a, b) \
    asm("mul.rn.f32x2 %0, %1, %2;" : "=l"(out) : "l"(a), "l"(b))

__device__ __forceinline__ float unpack_sum(unsigned long long v) {
    float lo = __uint_as_float((unsigned int)v);
    float hi = __uint_as_float((unsigned int)(v >> 32));
    return lo + hi;
}

// Two-level reduction state (all zero-initialized; counters self-reset).
__device__ double g_part[NBLK][3];     // per-CTA [Sm, S1, S2]
__device__ float  g_spt[NB];           // per-batch per_traj
__device__ unsigned int g_bcount[NB];  // per-batch arrival counters
__device__ unsigned int g_count;       // global arrival counter

// lengths may arrive as int64 or int32 (JAX x64 flag dependent).
__device__ __forceinline__ int get_len(const void* Lp, int b) {
    const long long* L64 = (const long long*)Lp;
    long long v0 = L64[0];
    if (v0 >= 1 && v0 <= (long long)TT) return (int)L64[b];
    return ((const int*)Lp)[b];
}

// ---------------------------------------------------------------------------
// Same structure as R14 (best: 13.6us kernel) but the inner displacement math
// uses packed f32x2: each (x,y) point is one 64-bit packed operand straight
// from SMEM; per pair cost = 1 FADD2 + 1 FFMA2 (x/y halves accumulate
// separately, summed once per lag at the end). Negated anchor built once per
// iteration via mul by packed -1.
// ---------------------------------------------------------------------------
__global__ void __launch_bounds__(NTHR, 7)
fused_kernel(const float* __restrict__ traj,
             const void*  __restrict__ lengths,
             const float* __restrict__ alpha_pred,
             float* __restrict__ out)
{
    __shared__ float4 sh4[TT / 2];     // positions 2k,2k+1 per float4
    __shared__ float  sacc[2][2][GL];  // [group-in-CTA][half][lag]

    const int blk  = blockIdx.x;
    const int b    = blk >> 4;        // batch
    const int part = blk & 15;        // lag slice (2 groups per CTA)

    const int   len   = get_len(lengths, b);
    const float alpha = alpha_pred[b];

    const float2*     sh  = (const float2*)sh4;
    const ulonglong2* sh8 = (const ulonglong2*)sh4;  // .x = point 2k, .y = point 2k+1

    const float4* rowq = (const float4*)(traj + (size_t)b * TT * 2);
    #pragma unroll
    for (int i = threadIdx.x; i < TT / 2; i += NTHR) sh4[i] = rowq[i];
    __syncthreads();

    const int warp = threadIdx.x >> 5;
    const int lane = threadIdx.x & 31;

    const int grp  = warp >> 1;                  // 0 or 1 within CTA
    const int half = warp & 1;                   // position half
    const int g    = part * 2 + grp;             // global group id [0,32)
    const int l0   = 1 + GL * g;                 // first lag (odd)

    int nmin = len - (l0 + GL - 1);
    if (nmin < 0) nmin = 0;
    if (nmin > PP) nmin = PP;
    int nmax = len - l0;
    if (nmax < 0) nmax = 0;
    if (nmax > PP) nmax = PP;

    const unsigned long long NEG1 = 0xBF800000BF800000ULL;  // (-1.f, -1.f)

    unsigned long long acc2[GL];                 // packed (sum_dx2, sum_dy2)
    #pragma unroll
    for (int j = 0; j < GL; j++) acc2[j] = 0ULL;

    const int imax = nmin >> 6;
    int i = half;

    // --- main region, unrolled x2 (blocks i and i+2; half stride is 2) ---
    for (; i + 2 < imax; i += 4) {
        const int pA = (i << 6) + (lane << 1);
        const int pB = pA + 128;
        const int kA = (pA + l0 - 1) >> 1;       // even window start
        const int kB = kA + 64;

        // hoist all 12 LDS.128 (independent)
        ulonglong2 aqA = sh8[pA >> 1];
        ulonglong2 A0 = sh8[kA],     A1 = sh8[kA + 1], A2 = sh8[kA + 2];
        ulonglong2 A3 = sh8[kA + 3], A4 = sh8[kA + 4];
        ulonglong2 aqB = sh8[pB >> 1];
        ulonglong2 B0 = sh8[kB],     B1 = sh8[kB + 1], B2 = sh8[kB + 2];
        ulonglong2 B3 = sh8[kB + 3], B4 = sh8[kB + 4];

        unsigned long long wa[10], wb[10];       // window pos l0-1 .. l0+8
        wa[0]=A0.x; wa[1]=A0.y; wa[2]=A1.x; wa[3]=A1.y; wa[4]=A2.x;
        wa[5]=A2.y; wa[6]=A3.x; wa[7]=A3.y; wa[8]=A4.x; wa[9]=A4.y;
        wb[0]=B0.x; wb[1]=B0.y; wb[2]=B1.x; wb[3]=B1.y; wb[4]=B2.x;
        wb[5]=B2.y; wb[6]=B3.x; wb[7]=B3.y; wb[8]=B4.x; wb[9]=B4.y;

        unsigned long long naA0, naA1, naB0, naB1;
        MUL_F32X2(naA0, aqA.x, NEG1);
        MUL_F32X2(naA1, aqA.y, NEG1);
        MUL_F32X2(naB0, aqB.x, NEG1);
        MUL_F32X2(naB1, aqB.y, NEG1);

        #pragma unroll
        for (int j = 0; j < GL; j++) {
            unsigned long long d0, d1, e0, e1;
            ADD_F32X2(d0, wa[j + 1], naA0);
            FMA_F32X2(acc2[j], d0, d0, acc2[j]);
            ADD_F32X2(d1, wa[j + 2], naA1);
            FMA_F32X2(acc2[j], d1, d1, acc2[j]);
            ADD_F32X2(e0, wb[j + 1], naB0);
            FMA_F32X2(acc2[j], e0, e0, acc2[j]);
            ADD_F32X2(e1, wb[j + 2], naB1);
            FMA_F32X2(acc2[j], e1, e1, acc2[j]);
        }
    }

    // --- leftover single block for this half ---
    if (i < imax) {
        const int p  = (i << 6) + (lane << 1);
        const int k0 = (p + l0 - 1) >> 1;
        ulonglong2 aq = sh8[p >> 1];
        ulonglong2 Q0 = sh8[k0],     Q1 = sh8[k0 + 1], Q2 = sh8[k0 + 2];
        ulonglong2 Q3 = sh8[k0 + 3], Q4 = sh8[k0 + 4];

        unsigned long long w[10];
        w[0]=Q0.x; w[1]=Q0.y; w[2]=Q1.x; w[3]=Q1.y; w[4]=Q2.x;
        w[5]=Q2.y; w[6]=Q3.x; w[7]=Q3.y; w[8]=Q4.x; w[9]=Q4.y;

        unsigned long long na0, na1;
        MUL_F32X2(na0, aq.x, NEG1);
        MUL_F32X2(na1, aq.y, NEG1);

        #pragma unroll
        for (int j = 0; j < GL; j++) {
            unsigned long long d0, d1;
            ADD_F32X2(d0, w[j + 1], na0);
            FMA_F32X2(acc2[j], d0, d0, acc2[j]);
            ADD_F32X2(d1, w[j + 2], na1);
            FMA_F32X2(acc2[j], d1, d1, acc2[j]);
        }
    }

    // --- unpack packed accumulators -> scalar ---
    float acc[GL];
    #pragma unroll
    for (int j = 0; j < GL; j++) acc[j] = unpack_sum(acc2[j]);

    // --- masked tail (half 1 only): scalar, < 64+GL positions ---
    if (half == 1) {
        for (int p = (imax << 6) + lane; p < nmax; p += 32) {
            float2 a = sh[p];
            #pragma unroll
            for (int j = 0; j < GL; j++) {
                int nj = len - (l0 + j);
                if (nj > PP) nj = PP;
                if (p < nj) {
                    float2 e = sh[p + l0 + j];
                    float dx = e.x - a.x, dy = e.y - a.y;
                    acc[j] += dx * dx + dy * dy;
                }
            }
        }
    }

    // --- warp reduce, stash per-half sums in SMEM ---
    #pragma unroll
    for (int j = 0; j < GL; j++) {
        #pragma unroll
        for (int o = 16; o > 0; o >>= 1)
            acc[j] += __shfl_xor_sync(0xffffffffu, acc[j], o);
    }
    if (lane == 0) {
        #pragma unroll
        for (int j = 0; j < GL; j++) sacc[grp][half][j] = acc[j];
    }
    __syncthreads();

    // ======================= tail: warp 0 only =======================
    if (warp == 0) {
        double sm = 0.0, s1 = 0.0, s2 = 0.0;
        if (lane < 16) {
            const int lg   = lane >> 3;
            const int jj   = lane & 7;
            const int lag  = 1 + GL * (part * 2 + lg) + jj;
            int nj = len - lag;
            if (nj < 0) nj = 0;
            if (nj > PP) nj = PP;
            const float tot = sacc[lg][0][jj] + sacc[lg][1][jj];
            const float msd = (nj > 0) ? tot / (float)nj : 0.f;
            const float r = logf(msd + 1e-8f) - alpha * logf((float)lag);
            if (len > lag) {
                sm = 1.0; s1 = (double)r; s2 = (double)r * (double)r;
            }
        }
        #pragma unroll
        for (int o = 16; o > 0; o >>= 1) {
            sm += __shfl_xor_sync(0xffffffffu, sm, o);
            s1 += __shfl_xor_sync(0xffffffffu, s1, o);
            s2 += __shfl_xor_sync(0xffffffffu, s2, o);
        }

        unsigned int oldb = 0u;
        if (lane == 0) {
            g_part[blk][0] = sm; g_part[blk][1] = s1; g_part[blk][2] = s2;
            __threadfence();
            oldb = atomicAdd(&g_bcount[b], 1u);
        }
        oldb = __shfl_sync(0xffffffffu, oldb, 0);

        if (oldb == CPB - 1) {
            // ---- per-batch last CTA: reduce 16 partials (lane-parallel) ----
            __threadfence();
            double Sm = 0.0, S1 = 0.0, S2 = 0.0;
            if (lane < CPB) {
                const int idx = b * CPB + lane;
                Sm = g_part[idx][0];
                S1 = g_part[idx][1];
                S2 = g_part[idx][2];
            }
            #pragma unroll
            for (int o = 16; o > 0; o >>= 1) {
                Sm += __shfl_xor_sync(0xffffffffu, Sm, o);
                S1 += __shfl_xor_sync(0xffffffffu, S1, o);
                S2 += __shfl_xor_sync(0xffffffffu, S2, o);
            }
            unsigned int oldg = 0u;
            if (lane == 0) {
                double denom = (Sm > 1.0) ? Sm : 1.0;
                double I = S1 / denom;
                double pt = (S2 - 2.0 * I * S1 + I * I * Sm) / denom;
                g_spt[b] = (float)pt;
                g_bcount[b] = 0;             // reset for next replay
                __threadfence();
                oldg = atomicAdd(&g_count, 1u);
            }
            oldg = __shfl_sync(0xffffffffu, oldg, 0);

            if (oldg == NB - 1) {
                // ---- global last: reduce 64 per-batch values ----
                __threadfence();
                float v = g_spt[lane] + g_spt[lane + 32];
                #pragma unroll
                for (int o = 16; o > 0; o >>= 1)
                    v += __shfl_xor_sync(0xffffffffu, v, o);
                if (lane == 0) {
                    g_count = 0;             // reset for next replay
                    __threadfence();
                    out[0] = v / (float)NB;
                }
            }
        }
    }
}

// ---------------------------------------------------------------------------
// Inputs: [0] alpha_pred f32[64], [1] trajectory f32[64,1024,2],
// [2] lengths int64/int32[64]. Output: 1 float.
// ---------------------------------------------------------------------------
extern "C" void kernel_launch(void* const* d_in, const int* in_sizes, int n_in,
                              void* d_out, int out_size)
{
    const float* alpha = (const float*)d_in[0];
    const float* traj  = (const float*)d_in[1];
    const void*  lens  = d_in[2];
    float* out = (float*)d_out;

    fused_kernel<<<NBLK, NTHR>>>(traj, lens, alpha, out);
}